// round 8
// baseline (speedup 1.0000x reference)
#include <cuda_runtime.h>

// ---- geometry ----
// kz=5 : 64 imgs 256x256, out 252x252. Block = 1 band: 22 input rows staged in smem,
//        2 halves x 9 output rows, 126 colpairs. 14 bands/img -> 896 blocks.
// kz=3 : 64 imgs 128x128, out 126x126. Register path: 63 colpairs x 7 chunks x R=18.
#define B5K        896
#define T3_THREADS 28224       // 64*63*7
#define B3_BLOCKS  111
#define NBLOCKS    (B5K + B3_BLOCKS)   // 1007

__device__ double g_part[NBLOCKS];
__device__ int    g_count;

typedef unsigned long long u64;

__device__ __forceinline__ u64 pack2(float lo, float hi) {
    u64 r; asm("mov.b64 %0, {%1,%2};" : "=l"(r) : "f"(lo), "f"(hi)); return r;
}
__device__ __forceinline__ u64 fma2(u64 a, u64 b, u64 c) {
    u64 d; asm("fma.rn.f32x2 %0, %1, %2, %3;" : "=l"(d) : "l"(a), "l"(b), "l"(c)); return d;
}
__device__ __forceinline__ u64 add2(u64 a, u64 b) {
    u64 d; asm("add.rn.f32x2 %0, %1, %2;" : "=l"(d) : "l"(a), "l"(b)); return d;
}
__device__ __forceinline__ u64 mul2(u64 a, u64 b) {
    u64 d; asm("mul.rn.f32x2 %0, %1, %2;" : "=l"(d) : "l"(a), "l"(b)); return d;
}
__device__ __forceinline__ void unpack2(u64 v, float& lo, float& hi) {
    asm("mov.b64 {%0,%1}, %2;" : "=f"(lo), "=f"(hi) : "l"(v));
}
__device__ __forceinline__ float lo2(u64 v){ float a,b; unpack2(v,a,b); return a; }
__device__ __forceinline__ float hi2(u64 v){ float a,b; unpack2(v,a,b); return b; }

// ---- kz5 horizontal stats from smem (8B-aligned, pairs come pre-packed) ----
__device__ __forceinline__ void hstats5s(const float* __restrict__ p,
                                         u64 two2, u64 neg12,
                                         u64& o0, u64& oc, u64& o2)
{
    u64 A = *reinterpret_cast<const u64*>(p);      // (f0,f1)
    u64 B = *reinterpret_cast<const u64*>(p + 2);  // (f2,f3)
    u64 C = *reinterpret_cast<const u64*>(p + 4);  // (f4,f5)
    u64 pk1 = pack2(hi2(A), lo2(B));               // (f1,f2)
    u64 pk3 = pack2(hi2(B), lo2(C));               // (f3,f4)
    u64 s0 = add2(add2(A, pk1), add2(B, pk3));
    s0 = add2(s0, C);
    u64 s2 = mul2(A, A);
    s2 = fma2(pk1, pk1, s2);
    s2 = fma2(B, B, s2);
    s2 = fma2(pk3, pk3, s2);
    s2 = fma2(C, C, s2);
    u64 d1 = fma2(neg12, pk1, pk3);
    u64 d2 = fma2(neg12, A, C);
    o0 = s0; oc = fma2(two2, d2, d1); o2 = s2;
}

// ---- kz3 horizontal stats from global (register path) ----
__device__ __forceinline__ void hstats3(const float* __restrict__ p,
                                        u64 neg12, u64& o0, u64& oc, u64& o2)
{
    float2 v0 = *reinterpret_cast<const float2*>(p);
    float2 v1 = *reinterpret_cast<const float2*>(p + 2);
    u64 pk0 = pack2(v0.x, v0.y);
    u64 pk1 = pack2(v0.y, v1.x);
    u64 pk2 = pack2(v1.x, v1.y);
    o0 = add2(add2(pk0, pk1), pk2);
    u64 s2 = mul2(pk0, pk0);
    s2 = fma2(pk1, pk1, s2);
    o2 = fma2(pk2, pk2, s2);
    oc = fma2(neg12, pk0, pk2);
}

__shared__ __align__(16) float tile5[22 * 256];   // 22.5 KB

// kz5 smem-staged band worker; returns per-thread partial
__device__ __forceinline__ float work5(const float* __restrict__ f1, int b, int tid)
{
    const int img  = b / 14;
    const int band = b - img * 14;
    const float* __restrict__ src = f1 + (size_t)img * 65536 + (size_t)(band * 18) * 256;

    // stage 22 rows x 256 cols = 1408 float4: 5 full passes + half pass (tid<128)
#pragma unroll
    for (int i = 0; i < 5; i++) {
        const int idx = tid + i * 256;
        reinterpret_cast<float4*>(tile5)[idx] =
            reinterpret_cast<const float4*>(src)[idx];
    }
    if (tid < 128) {
        const int idx = tid + 5 * 256;
        reinterpret_cast<float4*>(tile5)[idx] =
            reinterpret_cast<const float4*>(src)[idx];
    }
    __syncthreads();

    const int cg   = tid & 127;
    const int half = tid >> 7;
    if (cg >= 126) return 0.f;

    constexpr float ib = 1.f / 25.f;
    constexpr float il = 12.f / (25.f * 24.f);
    const u64 two2   = pack2(2.f, 2.f);
    const u64 neg12  = pack2(-1.f, -1.f);
    const u64 negib2 = pack2(-ib, -ib);
    const u64 negil2 = pack2(-il, -il);

    const float* p = tile5 + (half * 9) * 256 + cg * 2;

    u64 r0[5], rc[5], r2[5];
#pragma unroll
    for (int w = 0; w < 4; w++) {
        hstats5s(p, two2, neg12, r0[w], rc[w], r2[w]);
        p += 256;
    }

    u64 acc = 0ull;
#pragma unroll
    for (int i = 0; i < 9; i++) {
        const int sl = (i + 4) % 5;
        hstats5s(p, two2, neg12, r0[sl], rc[sl], r2[sl]);
        p += 256;
        const int a0 = i % 5, a1 = (i+1) % 5, a2 = (i+2) % 5, a3 = (i+3) % 5;
        u64 S0 = add2(add2(r0[a0], r0[a1]), add2(r0[a2], r0[a3]));
        S0 = add2(S0, r0[sl]);
        u64 S2 = add2(add2(r2[a0], r2[a1]), add2(r2[a2], r2[a3]));
        S2 = add2(S2, r2[sl]);
        u64 Sc = add2(add2(rc[a0], rc[a1]), add2(rc[a2], rc[a3]));
        Sc = add2(Sc, rc[sl]);
        u64 d1 = fma2(neg12, r0[a1], r0[a3]);
        u64 d2 = fma2(neg12, r0[a0], r0[sl]);
        u64 Sr = fma2(two2, d2, d1);
        u64 u = mul2(Sc, Sc); u = fma2(Sr, Sr, u);
        u64 v = mul2(S0, S0);
        u64 q = fma2(v, negib2, S2);
        acc   = add2(acc, fma2(u, negil2, q));
    }
    float a, bb; unpack2(acc, a, bb);
    return a + bb;
}

// kz3 register path: 2 output cols, 18 output rows, exact tiling
__device__ __forceinline__ float work3(const float* __restrict__ f0, int t)
{
    const int img   = t / 441;            // 63*7
    int rem         = t - img * 441;
    const int chunk = rem / 63;
    const int cg    = rem - chunk * 63;
    const float* __restrict__ p = f0 + (size_t)img * 16384
                                + (size_t)(chunk * 18) * 128 + cg * 2;

    constexpr float ib = 1.f / 9.f;
    constexpr float il = 12.f / (9.f * 8.f);
    const u64 neg12  = pack2(-1.f, -1.f);
    const u64 negib2 = pack2(-ib, -ib);
    const u64 negil2 = pack2(-il, -il);

    u64 r0[3], rc[3], r2[3];
#pragma unroll
    for (int w = 0; w < 2; w++) {
        hstats3(p, neg12, r0[w], rc[w], r2[w]);
        p += 128;
    }
    u64 acc = 0ull;
#pragma unroll
    for (int i = 0; i < 18; i++) {
        const int sl = (i + 2) % 3;
        hstats3(p, neg12, r0[sl], rc[sl], r2[sl]);
        p += 128;
        const int a0 = i % 3, a1 = (i + 1) % 3;
        u64 S0 = add2(add2(r0[a0], r0[a1]), r0[sl]);
        u64 S2 = add2(add2(r2[a0], r2[a1]), r2[sl]);
        u64 Sc = add2(add2(rc[a0], rc[a1]), rc[sl]);
        u64 Sr = fma2(neg12, r0[a0], r0[sl]);
        u64 u = mul2(Sc, Sc); u = fma2(Sr, Sr, u);
        u64 v = mul2(S0, S0);
        u64 q = fma2(v, negib2, S2);
        acc   = add2(acc, fma2(u, negil2, q));
    }
    float a, bb; unpack2(acc, a, bb);
    return a + bb;
}

__global__ void __launch_bounds__(256, 4) fused_kernel(const float* __restrict__ f0,
                                                       const float* __restrict__ f1,
                                                       float* __restrict__ out)
{
    const int tid = threadIdx.x;
    float acc = 0.f;
    double scale;

    if (blockIdx.x < B5K) {
        acc = work5(f1, blockIdx.x, tid);
        scale = 1.0 / (32.0 * 252.0 * 252.0);
    } else {
        const int t = (blockIdx.x - B5K) * 256 + tid;
        if (t < T3_THREADS) acc = work3(f0, t);
        scale = 1.0 / (32.0 * 126.0 * 126.0);
    }

#pragma unroll
    for (int o = 16; o > 0; o >>= 1) acc += __shfl_down_sync(0xffffffffu, acc, o);
    __shared__ float wsum[8];
    __shared__ bool  lastflag;
    if ((tid & 31) == 0) wsum[tid >> 5] = acc;
    __syncthreads();
    if (tid < 32) {
        float v = (tid < 8) ? wsum[tid] : 0.f;
#pragma unroll
        for (int o = 4; o > 0; o >>= 1) v += __shfl_down_sync(0xffffffffu, v, o);
        if (tid == 0) {
            g_part[blockIdx.x] = (double)v * scale;
            __threadfence();
            int done = atomicAdd(&g_count, 1);
            lastflag = (done == NBLOCKS - 1);
        }
    }
    __syncthreads();

    if (lastflag) {
        __threadfence();
        double s = 0.0;
        for (int i = tid; i < NBLOCKS; i += 256) s += g_part[i];
#pragma unroll
        for (int o = 16; o > 0; o >>= 1) s += __shfl_down_sync(0xffffffffu, s, o);
        __shared__ double ws[8];
        if ((tid & 31) == 0) ws[tid >> 5] = s;
        __syncthreads();
        if (tid < 32) {
            double v = (tid < 8) ? ws[tid] : 0.0;
#pragma unroll
            for (int o = 4; o > 0; o >>= 1) v += __shfl_down_sync(0xffffffffu, v, o);
            if (tid == 0) { out[0] = (float)v; g_count = 0; }
        }
    }
}

extern "C" void kernel_launch(void* const* d_in, const int* in_sizes, int n_in,
                              void* d_out, int out_size)
{
    const float* flow0 = (const float*)d_in[0];  // (32,2,128,128)
    const float* flow1 = (const float*)d_in[1];  // (32,2,256,256)
    if (n_in >= 2 && in_sizes[0] > in_sizes[1]) {
        const float* t = flow0; flow0 = flow1; flow1 = t;
    }
    fused_kernel<<<NBLOCKS, 256>>>(flow0, flow1, (float*)d_out);
}